// round 7
// baseline (speedup 1.0000x reference)
#include <cuda_runtime.h>
#include <math.h>

// CBOW negative-sampling loss.
//   d_in[0]: in_embed  float32 [100000, 128]
//   d_in[1]: out_embed float32 [100000, 128]
//   d_in[2]: context   int32   [B, 8]
//   d_in[3]: target    int32   [B]
//   d_in[4]: negatives int32   [B, 10]
// Output: float32 [B]
//
// Round 7 (= round 6 retried; previous bench was an infra failure).
// Same 2-elements-per-warp shape as R5 (best: 18.5us), but force
// occupancy up with __launch_bounds__(128, 12): reg budget 42/thread ->
// up to 48 warps/SM (vs 36 at regs=55). The kernel is latency-bound
// (DRAM 50%, issue 22% at occ 46%), so in-flight loads/SM = occ x MLP is
// the binding knob. u-row indices loaded after the ctx mean to shorten
// register liveness and avoid spills at the tighter budget.

#define CTX 8
#define NEG 10
#define D   128

__device__ __forceinline__ float log_sigmoid_fast(float x) {
    return fminf(x, 0.0f) - __logf(1.0f + __expf(-fabsf(x)));
}

__device__ __forceinline__ float dot4(float4 a, float4 b) {
    return a.x * b.x + a.y * b.y + a.z * b.z + a.w * b.w;
}

__global__ __launch_bounds__(128, 12) void cbow_neg_kernel(
    const float* __restrict__ in_embed,
    const float* __restrict__ out_embed,
    const int*   __restrict__ context,
    const int*   __restrict__ target,
    const int*   __restrict__ negatives,
    float*       __restrict__ out,
    int B)
{
    const int lane   = threadIdx.x & 31;
    const int warpId = (blockIdx.x * blockDim.x + threadIdx.x) >> 5;
    const int group  = lane >> 4;            // 0..1: element within warp
    const int sub    = lane & 15;            // 0..15: lane within group
    const int e      = warpId * 2 + group;   // batch element
    if (e >= B) return;                      // B even, warp-uniform exit

    // ---- context indices (L1-broadcast within each half-warp) ----
    int cidx[CTX];
    #pragma unroll
    for (int c = 0; c < CTX; c++) cidx[c] = __ldg(&context[e * CTX + c]);

    // ---- v = mean of 8 context rows; lane holds slots {sub, sub+16} ----
    float4 v0, v1;
    {
        const float4* r = reinterpret_cast<const float4*>(
                              in_embed + (size_t)cidx[0] * D);
        v0 = __ldg(r + sub);
        v1 = __ldg(r + sub + 16);
    }
    #pragma unroll
    for (int c = 1; c < CTX; c++) {
        const float4* r = reinterpret_cast<const float4*>(
                              in_embed + (size_t)cidx[c] * D);
        const float4 a = __ldg(r + sub);
        const float4 b = __ldg(r + sub + 16);
        v0.x += a.x; v0.y += a.y; v0.z += a.z; v0.w += a.w;
        v1.x += b.x; v1.y += b.y; v1.z += b.z; v1.w += b.w;
    }
    const float inv = 1.0f / (float)CTX;
    v0.x *= inv; v0.y *= inv; v0.z *= inv; v0.w *= inv;
    v1.x *= inv; v1.y *= inv; v1.z *= inv; v1.w *= inv;

    // ---- u-row indices (short liveness: loaded only now) ----
    int ridx[NEG + 1];
    ridx[0] = __ldg(&target[e]);
    #pragma unroll
    for (int k = 0; k < NEG; k++) ridx[1 + k] = __ldg(&negatives[e * NEG + k]);

    // ---- 11 per-lane partial dots (target + 10 negatives) ----
    float s[NEG + 1];
    #pragma unroll
    for (int i = 0; i < NEG + 1; i++) {
        const float4* u = reinterpret_cast<const float4*>(
                              out_embed + (size_t)ridx[i] * D);
        const float4 a = __ldg(u + sub);
        const float4 b = __ldg(u + sub + 16);
        s[i] = dot4(v0, a) + dot4(v1, b);
    }

    // ---- reduce each score within the 16-lane group (4 stages) ----
    #pragma unroll
    for (int i = 0; i < NEG + 1; i++) {
        float x = s[i];
        x += __shfl_xor_sync(0xffffffffu, x, 8);
        x += __shfl_xor_sync(0xffffffffu, x, 4);
        x += __shfl_xor_sync(0xffffffffu, x, 2);
        x += __shfl_xor_sync(0xffffffffu, x, 1);
        s[i] = x;
    }

    // ---- epilogue: 2 group leaders per warp in parallel lanes ----
    if (sub == 0) {
        float acc = log_sigmoid_fast(s[0]);
        #pragma unroll
        for (int k = 0; k < NEG; k++)
            acc += log_sigmoid_fast(-s[1 + k]);
        out[e] = -acc;
    }
}

extern "C" void kernel_launch(void* const* d_in, const int* in_sizes, int n_in,
                              void* d_out, int out_size)
{
    const float* in_embed  = (const float*)d_in[0];
    const float* out_embed = (const float*)d_in[1];
    const int*   context   = (const int*)d_in[2];
    const int*   target    = (const int*)d_in[3];
    const int*   negatives = (const int*)d_in[4];
    float*       out       = (float*)d_out;

    const int B = out_size;                       // 16384
    const int warps = (B + 1) / 2;                // 2 elements per warp
    const int threads = 128;                      // 4 warps/block
    const int blocks = (warps * 32 + threads - 1) / threads;   // 2048
    cbow_neg_kernel<<<blocks, threads>>>(in_embed, out_embed, context, target,
                                         negatives, out, B);
}